// round 6
// baseline (speedup 1.0000x reference)
#include <cuda_runtime.h>
#include <cstdint>

#define BB 8
#define CC 64
#define OO 64
#define HH 96
#define WW 96
#define HW (HH*WW)          // 9216
#define K2 9
#define NOFF 18

typedef unsigned long long ull;
typedef ulonglong2 ull2;

#define PACKF2(d, lo, hi) asm("mov.b64 %0, {%1,%2};" : "=l"(d) : "f"(lo), "f"(hi))
#define UNPKF2(lo, hi, s) asm("mov.b64 {%0,%1}, %2;" : "=f"(lo), "=f"(hi) : "l"(s))
#define FMA2(d, a, b, c)  asm("fma.rn.f32x2 %0, %1, %2, %3;" : "=l"(d) : "l"(a), "l"(b), "l"(c))
#define BAR_SYNC(id)   asm volatile("bar.sync %0, 384;"   :: "r"(id) : "memory")
#define BAR_ARRIVE(id) asm volatile("bar.arrive %0, 384;" :: "r"(id) : "memory")

// ---------------- scratch ----------------------------------------------------
__device__ float g_xt[BB * HW * CC];          // x in NHWC (~18.9 MB)
__device__ float g_offs[BB * HW * NOFF];      // offsets, pixel-major (~5.3 MB)
__device__ float g_wt[K2 * CC * OO];          // conv_w as [k][c][o]
__device__ float g_owt[CC * K2 * 20];         // offset_w as [c][tap][j pad 20]

// ---------------- kernel T1: NCHW -> NHWC transpose -------------------------
__global__ void transpose_x_kernel(const float* __restrict__ x, float* __restrict__ xt) {
    __shared__ float tile[32][33];
    int blk = blockIdx.x;            // 8 * 2 * 288
    int pt  = blk % 288;
    int ct  = (blk / 288) & 1;
    int b   = blk / 576;
    int lx = threadIdx.x & 31, ly = threadIdx.x >> 5;
    int p0 = pt * 32, c0 = ct * 32;
    const float* xb = x + (size_t)(b * CC + c0) * HW + p0;
#pragma unroll
    for (int i = 0; i < 4; i++) {
        int cc = ly + 8 * i;
        tile[cc][lx] = xb[(size_t)cc * HW + lx];
    }
    __syncthreads();
    float* xo = xt + (size_t)(b * HW + p0) * CC + c0;
#pragma unroll
    for (int i = 0; i < 4; i++) {
        int pp = ly + 8 * i;
        xo[(size_t)pp * CC + lx] = tile[lx][pp];
    }
}

// ---------------- kernel T2: weight re-layouts -------------------------------
__global__ void build_weights_kernel(const float* __restrict__ cw,
                                     const float* __restrict__ ow,
                                     float* __restrict__ wt,
                                     float* __restrict__ owt) {
    int idx = blockIdx.x * 256 + threadIdx.x;
    if (idx < OO * CC * K2) {
        int o = idx / (CC * K2);
        int r = idx % (CC * K2);
        int c = r / K2;
        int k = r % K2;
        wt[(k * CC + c) * OO + o] = cw[idx];
    }
    if (idx < NOFF * CC * K2) {
        int j = idx / (CC * K2);
        int r = idx % (CC * K2);
        int c = r / K2;
        int k = r % K2;
        owt[(c * K2 + k) * 20 + j] = ow[idx];
    }
}

// ---------------- kernel 1: offset conv (f32x2), 1 px / thread --------------
__global__ void __launch_bounds__(256) offset_conv_kernel(
    const float* __restrict__ x, const float* __restrict__ owt,
    const float* __restrict__ ob, float* __restrict__ offs)
{
    __shared__ float ws[CC * K2 * 20];
    __shared__ float bs[NOFF];
    int tid = threadIdx.x;
    for (int i = tid; i < CC * K2 * 20; i += 256) ws[i] = owt[i];
    if (tid < NOFF) bs[tid] = ob[tid];
    __syncthreads();

    int flat = blockIdx.x * 256 + tid;
    int b = flat / HW, p = flat % HW;
    int h = p / WW, w = p % WW;
    const float* x0 = x + (size_t)b * CC * HW;

    ull a0[9];
#pragma unroll
    for (int j = 0; j < 9; j++) a0[j] = 0ull;

    int yy[3], xx[3]; bool vy[3], vx[3];
#pragma unroll
    for (int d = 0; d < 3; d++) {
        yy[d] = h + d - 1; vy[d] = (unsigned)yy[d] < (unsigned)HH;
        xx[d] = w + d - 1; vx[d] = (unsigned)xx[d] < (unsigned)WW;
    }

    for (int c = 0; c < CC; c++) {
        float xv0[9];
        const float* xc0 = x0 + (size_t)c * HW;
#pragma unroll
        for (int dy = 0; dy < 3; dy++)
#pragma unroll
            for (int dx = 0; dx < 3; dx++) {
                int i = dy * 3 + dx;
                bool v = vy[dy] && vx[dx];
                xv0[i] = v ? xc0[yy[dy] * WW + xx[dx]] : 0.f;
            }
#pragma unroll
        for (int i = 0; i < 9; i++) {
            const float* row = ws + (c * K2 + i) * 20;
            ull s0;
            PACKF2(s0, xv0[i], xv0[i]);
#pragma unroll
            for (int j = 0; j < 9; j++) {
                ull wv = *(const ull*)(row + 2 * j);
                FMA2(a0[j], s0, wv, a0[j]);
            }
        }
    }
    float* o0 = offs + (size_t)flat * NOFF;
#pragma unroll
    for (int j = 0; j < 9; j++) {
        float lo, hi;
        UNPKF2(lo, hi, a0[j]);
        *(float2*)(o0 + 2 * j) = make_float2(lo + bs[2 * j], hi + bs[2 * j + 1]);
    }
}

// ---------------- kernel 2: warp-specialized fused kernel -------------------
// 384 threads: tid 0..255 consumers (GEMM), tid 256..383 producers (gather).
// Tile 128 px x 64 out. Double-buffered samples + weights.
// Barriers: full[buf]=1+buf  (producers arrive, consumers sync)
//           empty[buf]=3+buf (consumers arrive, producers sync)
#define SAMP_ST 68
#define SAMP_SZ (128 * SAMP_ST)                      // 8704 floats
#define SMEM_FUSED ((2 * SAMP_SZ + 2 * 4096) * 4)    // 102400 B

__global__ void __launch_bounds__(384, 2) fused_deform_kernel(
    const float* __restrict__ xt, const float* __restrict__ offs,
    const float* __restrict__ wt, const float* __restrict__ cb,
    float* __restrict__ out)
{
    extern __shared__ float sm[];
    float* samp = sm;                    // 2 * 8704
    float* wsb  = sm + 2 * SAMP_SZ;      // 2 * 4096

    int tid = threadIdx.x;
    int b   = blockIdx.x / 72;
    int p0  = (blockIdx.x % 72) * 128;

    if (tid >= 256) {
        // ================= producers: 4 warps =================
        int pt   = tid - 256;
        int warp = pt >> 5;
        int lane = pt & 31;
        int c2   = 2 * lane;
        const float* xt_b   = xt   + (size_t)b * HW * CC;
        const float* offs_p = offs + ((size_t)(b * HW + p0)) * NOFF;

        for (int k = 0; k < 9; k++) {
            int buf = k & 1;
            if (k >= 2) BAR_SYNC(3 + buf);

            // stage this tap's 64x64 weights (16 KB)
            {
                const float4* wsrc = (const float4*)(wt + k * 4096);
                float4* wdst = (float4*)(wsb + buf * 4096);
#pragma unroll
                for (int r = 0; r < 8; r++) wdst[pt + 128 * r] = wsrc[pt + 128 * r];
            }
            // fill 128 px of samples (32 per warp)
            float* sb = samp + buf * SAMP_SZ;
            int kdy = k / 3 - 1, kdx = k % 3 - 1;
#pragma unroll 2
            for (int j = 0; j < 32; j++) {
                int px = 4 * j + warp;
                int p = p0 + px;
                int h = p / WW, w = p - h * WW;
                float2 od = *(const float2*)(offs_p + px * NOFF + 2 * k);
                float py  = (float)(h + kdy) + od.x;
                float pxf = (float)(w + kdx) + od.y;
                float fy = floorf(py), fx = floorf(pxf);
                int y0 = (int)fy, x0 = (int)fx;
                float wy = py - fy, wx = pxf - fx;
                bool vy0 = (unsigned)y0 < (unsigned)HH;
                bool vy1 = (unsigned)(y0 + 1) < (unsigned)HH;
                bool vx0 = (unsigned)x0 < (unsigned)WW;
                bool vx1 = (unsigned)(x0 + 1) < (unsigned)WW;
                const float* base = xt_b + ((ptrdiff_t)y0 * WW + x0) * CC + c2;
                float2 z = make_float2(0.f, 0.f);
                float2 g00 = (vy0 && vx0) ? *(const float2*)(base)              : z;
                float2 g01 = (vy0 && vx1) ? *(const float2*)(base + CC)         : z;
                float2 g10 = (vy1 && vx0) ? *(const float2*)(base + WW*CC)      : z;
                float2 g11 = (vy1 && vx1) ? *(const float2*)(base + WW*CC + CC) : z;
                float w00 = (1.f - wy) * (1.f - wx);
                float w01 = (1.f - wy) * wx;
                float w10 = wy * (1.f - wx);
                float w11 = wy * wx;
                float sx = g00.x * w00 + g01.x * w01 + g10.x * w10 + g11.x * w11;
                float sy = g00.y * w00 + g01.y * w01 + g10.y * w10 + g11.y * w11;
                *(float2*)(sb + px * SAMP_ST + c2) = make_float2(sx, sy);
            }
            BAR_ARRIVE(1 + buf);
        }
    } else {
        // ================= consumers: 8 warps =================
        int tx  = tid & 7;          // out group: o = tx*8 .. +7
        int ty  = tid >> 3;         // px block: px = ty*4 .. +3
        int txo = tx * 8;

        ull acc[4][4];
#pragma unroll
        for (int i = 0; i < 4; i++)
#pragma unroll
            for (int j = 0; j < 4; j++) acc[i][j] = 0ull;

        const float* sbase0 = samp + (ty * 4) * SAMP_ST;

        for (int k = 0; k < 9; k++) {
            int buf = k & 1;
            BAR_SYNC(1 + buf);
            const float* sb = sbase0 + buf * SAMP_SZ;
            const float* wb = wsb + buf * 4096;
#pragma unroll 2
            for (int cc = 0; cc < 64; cc += 4) {
                float4 sv[4];
#pragma unroll
                for (int i = 0; i < 4; i++)
                    sv[i] = *(const float4*)(sb + i * SAMP_ST + cc);
#pragma unroll
                for (int r = 0; r < 4; r++) {
                    ull2 wA = *(const ull2*)(wb + (cc + r) * 64 + txo);
                    ull2 wB = *(const ull2*)(wb + (cc + r) * 64 + txo + 4);
#pragma unroll
                    for (int i = 0; i < 4; i++) {
                        float s = (r == 0) ? sv[i].x : (r == 1) ? sv[i].y :
                                  (r == 2) ? sv[i].z : sv[i].w;
                        ull ss;
                        PACKF2(ss, s, s);
                        FMA2(acc[i][0], ss, wA.x, acc[i][0]);
                        FMA2(acc[i][1], ss, wA.y, acc[i][1]);
                        FMA2(acc[i][2], ss, wB.x, acc[i][2]);
                        FMA2(acc[i][3], ss, wB.y, acc[i][3]);
                    }
                }
            }
            BAR_ARRIVE(3 + buf);
        }

        // epilogue: px = p0 + ty*4 + i (contiguous 4), outs txo..txo+7
        int p = p0 + ty * 4;
#pragma unroll
        for (int j = 0; j < 4; j++) {
            float bL = cb[txo + 2 * j];
            float bH = cb[txo + 2 * j + 1];
            float4 vlo, vhi;
            float lo, hi;
            UNPKF2(lo, hi, acc[0][j]); vlo.x = lo + bL; vhi.x = hi + bH;
            UNPKF2(lo, hi, acc[1][j]); vlo.y = lo + bL; vhi.y = hi + bH;
            UNPKF2(lo, hi, acc[2][j]); vlo.z = lo + bL; vhi.z = hi + bH;
            UNPKF2(lo, hi, acc[3][j]); vlo.w = lo + bL; vhi.w = hi + bH;
            float* oL = out + (size_t)(b * OO + txo + 2 * j) * HW + p;
            *(float4*)oL = vlo;
            *(float4*)(oL + HW) = vhi;
        }
    }
}

// ---------------- launch ------------------------------------------------------
extern "C" void kernel_launch(void* const* d_in, const int* in_sizes, int n_in,
                              void* d_out, int out_size) {
    const float* x  = (const float*)d_in[0];
    const float* ow = (const float*)d_in[1];
    const float* ob = (const float*)d_in[2];
    const float* cw = (const float*)d_in[3];
    const float* cb = (const float*)d_in[4];
    float* out = (float*)d_out;

    float *xt, *offs, *wt, *owt;
    cudaGetSymbolAddress((void**)&xt,   g_xt);
    cudaGetSymbolAddress((void**)&offs, g_offs);
    cudaGetSymbolAddress((void**)&wt,   g_wt);
    cudaGetSymbolAddress((void**)&owt,  g_owt);

    cudaFuncSetAttribute(fused_deform_kernel,
                         cudaFuncAttributeMaxDynamicSharedMemorySize, SMEM_FUSED);

    transpose_x_kernel<<<4608, 256>>>(x, xt);
    build_weights_kernel<<<144, 256>>>(cw, ow, wt, owt);
    offset_conv_kernel<<<288, 256>>>(x, owt, ob, offs);
    fused_deform_kernel<<<576, 384, SMEM_FUSED>>>(xt, offs, wt, cb, out);
}

// round 8
// speedup vs baseline: 1.6110x; 1.6110x over previous
#include <cuda_runtime.h>
#include <cuda_bf16.h>
#include <cstdint>

#define BB 8
#define CC 64
#define OO 64
#define HH 96
#define WW 96
#define HW (HH*WW)
#define K2 9
#define NOFF 18

typedef unsigned long long ull;
typedef unsigned short ushort_t;

#define PACKF2(d, lo, hi) asm("mov.b64 %0, {%1,%2};" : "=l"(d) : "f"(lo), "f"(hi))
#define UNPKF2(lo, hi, s) asm("mov.b64 {%0,%1}, %2;" : "=f"(lo), "=f"(hi) : "l"(s))
#define FMA2(d, a, b, c)  asm("fma.rn.f32x2 %0, %1, %2, %3;" : "=l"(d) : "l"(a), "l"(b), "l"(c))

__device__ __forceinline__ uint32_t smem_u32(const void* p) {
    uint32_t a;
    asm("{ .reg .u64 t; cvta.to.shared.u64 t, %1; cvt.u32.u64 %0, t; }" : "=r"(a) : "l"(p));
    return a;
}

#define LDSM_X4(r0, r1, r2, r3, addr) \
    asm volatile("ldmatrix.sync.aligned.m8n8.x4.shared.b16 {%0,%1,%2,%3}, [%4];" \
                 : "=r"(r0), "=r"(r1), "=r"(r2), "=r"(r3) : "r"(addr))

#define MMA16816(ac, a0, a1, a2, a3, b0, b1) \
    asm volatile("mma.sync.aligned.m16n8k16.row.col.f32.bf16.bf16.f32 " \
                 "{%0,%1,%2,%3}, {%4,%5,%6,%7}, {%8,%9}, {%0,%1,%2,%3};" \
                 : "+f"((ac)[0]), "+f"((ac)[1]), "+f"((ac)[2]), "+f"((ac)[3]) \
                 : "r"(a0), "r"(a1), "r"(a2), "r"(a3), "r"(b0), "r"(b1))

// ---------------- scratch -----------------------------------------------------
__device__ float g_xt[BB * HW * CC];
__device__ float g_offs[BB * HW * NOFF];
__device__ float g_owt[CC * K2 * 20];
__device__ ushort_t g_bst[K2 * 2 * OO * 72];   // conv_w bf16 [tap][split hi/lo][o][72]

// ---------------- transpose NCHW -> NHWC --------------------------------------
__global__ void transpose_x_kernel(const float* __restrict__ x, float* __restrict__ xt) {
    __shared__ float tile[32][33];
    int blk = blockIdx.x;
    int pt = blk % 288, ct = (blk / 288) & 1, b = blk / 576;
    int lx = threadIdx.x & 31, ly = threadIdx.x >> 5;
    int p0 = pt * 32, c0 = ct * 32;
    const float* xb = x + (size_t)(b * CC + c0) * HW + p0;
#pragma unroll
    for (int i = 0; i < 4; i++) {
        int cc = ly + 8 * i;
        tile[cc][lx] = xb[(size_t)cc * HW + lx];
    }
    __syncthreads();
    float* xo = xt + (size_t)(b * HW + p0) * CC + c0;
#pragma unroll
    for (int i = 0; i < 4; i++) {
        int pp = ly + 8 * i;
        xo[(size_t)pp * CC + lx] = tile[lx][pp];
    }
}

// ---------------- weight prep ---------------------------------------------------
__global__ void build_weights_kernel(const float* __restrict__ cw,
                                     const float* __restrict__ ow,
                                     ushort_t* __restrict__ bst,
                                     float* __restrict__ owt) {
    int idx = blockIdx.x * 256 + threadIdx.x;
    if (idx < K2 * OO * CC) {
        int k = idx / (OO * CC);
        int r = idx % (OO * CC);
        int o = r / CC;
        int c = r % CC;
        float v = cw[(size_t)(o * CC + c) * K2 + k];
        __nv_bfloat16 h = __float2bfloat16(v);
        __nv_bfloat16 l = __float2bfloat16(v - __bfloat162float(h));
        bst[((size_t)(k * 2 + 0) * OO + o) * 72 + c] = *(ushort_t*)&h;
        bst[((size_t)(k * 2 + 1) * OO + o) * 72 + c] = *(ushort_t*)&l;
    }
    if (idx < NOFF * CC * K2) {
        int j = idx / (CC * K2);
        int r = idx % (CC * K2);
        int c = r / K2;
        int k = r % K2;
        owt[(c * K2 + k) * 20 + j] = ow[idx];
    }
}

// ---------------- offset conv (f32x2) ------------------------------------------
__global__ void __launch_bounds__(256) offset_conv_kernel(
    const float* __restrict__ x, const float* __restrict__ owt,
    const float* __restrict__ ob, float* __restrict__ offs)
{
    __shared__ float ws[CC * K2 * 20];
    __shared__ float bs[NOFF];
    int tid = threadIdx.x;
    for (int i = tid; i < CC * K2 * 20; i += 256) ws[i] = owt[i];
    if (tid < NOFF) bs[tid] = ob[tid];
    __syncthreads();

    int flat = blockIdx.x * 256 + tid;
    int b = flat / HW, p = flat % HW;
    int h = p / WW, w = p % WW;
    const float* x0 = x + (size_t)b * CC * HW;

    ull a0[9];
#pragma unroll
    for (int j = 0; j < 9; j++) a0[j] = 0ull;

    int yy[3], xx[3]; bool vy[3], vx[3];
#pragma unroll
    for (int d = 0; d < 3; d++) {
        yy[d] = h + d - 1; vy[d] = (unsigned)yy[d] < (unsigned)HH;
        xx[d] = w + d - 1; vx[d] = (unsigned)xx[d] < (unsigned)WW;
    }
    for (int c = 0; c < CC; c++) {
        float xv[9];
        const float* xc = x0 + (size_t)c * HW;
#pragma unroll
        for (int dy = 0; dy < 3; dy++)
#pragma unroll
            for (int dx = 0; dx < 3; dx++) {
                int i = dy * 3 + dx;
                xv[i] = (vy[dy] && vx[dx]) ? xc[yy[dy] * WW + xx[dx]] : 0.f;
            }
#pragma unroll
        for (int i = 0; i < 9; i++) {
            const float* row = ws + (c * K2 + i) * 20;
            ull s0;
            PACKF2(s0, xv[i], xv[i]);
#pragma unroll
            for (int j = 0; j < 9; j++) {
                ull wv = *(const ull*)(row + 2 * j);
                FMA2(a0[j], s0, wv, a0[j]);
            }
        }
    }
    float* o0 = offs + (size_t)flat * NOFF;
#pragma unroll
    for (int j = 0; j < 9; j++) {
        float lo, hi;
        UNPKF2(lo, hi, a0[j]);
        *(float2*)(o0 + 2 * j) = make_float2(lo + bs[2 * j], hi + bs[2 * j + 1]);
    }
}

// ---------------- fused: gather -> bf16 split -> HMMA.16816 ---------------------
// 256 threads, tile M=128 px x N=64 out. smem: A hi/lo [128][72] bf16,
// B hi/lo [64][72] bf16. Warp w: m-tile w (16 px) x all 8 n8-tiles.
#define SM_A 0
#define A_SPLIT 18432            // bytes per A split buffer (128*144)
#define SM_B 36864
#define B_SPLIT 9216             // bytes per B split (64*144)
#define SM_TOT (SM_B + 2 * B_SPLIT)   // 55296

__global__ void __launch_bounds__(256, 2)
fused_mma_kernel(const float* __restrict__ xt, const float* __restrict__ offs,
                 const ushort_t* __restrict__ bst,
                 const float* __restrict__ cb, float* __restrict__ out)
{
    extern __shared__ char smc[];
    uint32_t sbase = smem_u32(smc);
    int tid = threadIdx.x, wid = tid >> 5, lane = tid & 31;
    int b  = blockIdx.x / 72;
    int p0 = (blockIdx.x % 72) * 128;

    const float* xt_b   = xt   + (size_t)b * HW * CC;
    const float* offs_b = offs + ((size_t)(b * HW + p0)) * NOFF;

    float acc[8][4];
#pragma unroll
    for (int i = 0; i < 8; i++)
#pragma unroll
        for (int j = 0; j < 4; j++) acc[i][j] = 0.f;

    int lr = lane & 7;
    // ldmatrix lane-address offsets (bytes), stride 144 B/row
    uint32_t aoff = (uint32_t)((lr + ((lane >> 3) & 1) * 8) * 144 + (lane >> 4) * 16);
    uint32_t boff = (uint32_t)((lr + (lane >> 4) * 8) * 144 + ((lane >> 3) & 1) * 16);
    uint32_t a_warp = sbase + SM_A + (uint32_t)(wid * 16 * 144) + aoff;
    uint32_t b_base = sbase + SM_B + boff;
    int c2 = 2 * lane;

    for (int k = 0; k < 9; k++) {
        // stage B hi+lo for this tap (1152 uint4)
        {
            const uint4* src = (const uint4*)(bst + (size_t)k * 9216);
            uint4* dst = (uint4*)(smc + SM_B);
            for (int i = tid; i < 1152; i += 256) dst[i] = src[i];
        }
        // fill A: gather + bilinear + bf16 split, 16 px per warp
        int kdy = k / 3 - 1, kdx = k % 3 - 1;
#pragma unroll 2
        for (int j = 0; j < 16; j++) {
            int px = wid + 8 * j;
            int p = p0 + px;
            int h = p / WW, w = p - h * WW;
            float2 od = *(const float2*)(offs_b + px * NOFF + 2 * k);
            float py = (float)(h + kdy) + od.x;
            float qx = (float)(w + kdx) + od.y;
            float fy = floorf(py), fx = floorf(qx);
            int y0 = (int)fy, x0 = (int)fx;
            float wy = py - fy, wx = qx - fx;
            bool vy0 = (unsigned)y0 < (unsigned)HH;
            bool vy1 = (unsigned)(y0 + 1) < (unsigned)HH;
            bool vx0 = (unsigned)x0 < (unsigned)WW;
            bool vx1 = (unsigned)(x0 + 1) < (unsigned)WW;
            const float* base = xt_b + ((ptrdiff_t)y0 * WW + x0) * CC + c2;
            float2 z = make_float2(0.f, 0.f);
            float2 g00 = (vy0 && vx0) ? *(const float2*)(base)              : z;
            float2 g01 = (vy0 && vx1) ? *(const float2*)(base + CC)         : z;
            float2 g10 = (vy1 && vx0) ? *(const float2*)(base + WW*CC)      : z;
            float2 g11 = (vy1 && vx1) ? *(const float2*)(base + WW*CC + CC) : z;
            float w00 = (1.f - wy) * (1.f - wx);
            float w01 = (1.f - wy) * wx;
            float w10 = wy * (1.f - wx);
            float w11 = wy * wx;
            float sx = g00.x*w00 + g01.x*w01 + g10.x*w10 + g11.x*w11;
            float sy = g00.y*w00 + g01.y*w01 + g10.y*w10 + g11.y*w11;
            uint32_t hp, lp;
            asm("cvt.rn.bf16x2.f32 %0, %1, %2;" : "=r"(hp) : "f"(sy), "f"(sx));
            float hx = __uint_as_float(hp << 16);
            float hy = __uint_as_float(hp & 0xffff0000u);
            asm("cvt.rn.bf16x2.f32 %0, %1, %2;" : "=r"(lp) : "f"(sy - hy), "f"(sx - hx));
            uint32_t ao = (uint32_t)(px * 144 + lane * 4);
            *(uint32_t*)(smc + SM_A + ao)           = hp;
            *(uint32_t*)(smc + SM_A + A_SPLIT + ao) = lp;
        }
        __syncthreads();

        // GEMM: 3 splits x 4 k-steps x 8 n-tiles
#pragma unroll
        for (int s = 0; s < 3; s++) {
            uint32_t aB = a_warp + ((s == 1) ? A_SPLIT : 0);
            uint32_t bB = b_base + ((s == 2) ? B_SPLIT : 0);
#pragma unroll
            for (int ks = 0; ks < 4; ks++) {
                uint32_t a0, a1, a2, a3;
                LDSM_X4(a0, a1, a2, a3, aB + ks * 32);
                uint32_t bf[4][4];
#pragma unroll
                for (int q = 0; q < 4; q++)
                    LDSM_X4(bf[q][0], bf[q][1], bf[q][2], bf[q][3],
                            bB + (uint32_t)(q * 2304) + ks * 32);
#pragma unroll
                for (int nt = 0; nt < 8; nt++) {
                    uint32_t* bq = bf[nt >> 1];
                    int e = (nt & 1) * 2;
                    MMA16816(acc[nt], a0, a1, a2, a3, bq[e], bq[e + 1]);
                }
            }
        }
        __syncthreads();
    }

    // epilogue: warp m-tile wid*16; d0/d1 -> (m=lane>>2, n=2*(lane&3)), d2/d3 -> m+8
    int px0 = p0 + wid * 16 + (lane >> 2);
    int ob0 = 2 * (lane & 3);
    float* outb = out + (size_t)b * OO * HW;
#pragma unroll
    for (int nt = 0; nt < 8; nt++) {
        int o = nt * 8 + ob0;
        float b0 = cb[o], b1 = cb[o + 1];
        outb[(size_t)o * HW + px0]           = acc[nt][0] + b0;
        outb[(size_t)(o + 1) * HW + px0]     = acc[nt][1] + b1;
        outb[(size_t)o * HW + px0 + 8]       = acc[nt][2] + b0;
        outb[(size_t)(o + 1) * HW + px0 + 8] = acc[nt][3] + b1;
    }
}

// ---------------- launch ---------------------------------------------------------
extern "C" void kernel_launch(void* const* d_in, const int* in_sizes, int n_in,
                              void* d_out, int out_size) {
    const float* x  = (const float*)d_in[0];
    const float* ow = (const float*)d_in[1];
    const float* ob = (const float*)d_in[2];
    const float* cw = (const float*)d_in[3];
    const float* cb = (const float*)d_in[4];
    float* out = (float*)d_out;

    float *xt, *offs, *owt;
    ushort_t* bst;
    cudaGetSymbolAddress((void**)&xt,   g_xt);
    cudaGetSymbolAddress((void**)&offs, g_offs);
    cudaGetSymbolAddress((void**)&owt,  g_owt);
    cudaGetSymbolAddress((void**)&bst,  g_bst);

    cudaFuncSetAttribute(fused_mma_kernel,
                         cudaFuncAttributeMaxDynamicSharedMemorySize, SM_TOT);

    transpose_x_kernel<<<4608, 256>>>(x, xt);
    build_weights_kernel<<<144, 256>>>(cw, ow, bst, owt);
    offset_conv_kernel<<<288, 256>>>(x, owt, ob, offs);
    fused_mma_kernel<<<576, 256, SM_TOT>>>(xt, offs, bst, cb, out);
}

// round 9
// speedup vs baseline: 1.8022x; 1.1187x over previous
#include <cuda_runtime.h>
#include <cuda_bf16.h>
#include <cstdint>

#define BB 8
#define CC 64
#define OO 64
#define HH 96
#define WW 96
#define HW (HH*WW)
#define K2 9
#define NOFF 18
#define WP 100              // padded width/height
#define XTB (WP*WP*CC)      // padded per-batch xt size (640000)

typedef unsigned long long ull;
typedef unsigned short ushort_t;

#define PACKF2(d, lo, hi) asm("mov.b64 %0, {%1,%2};" : "=l"(d) : "f"(lo), "f"(hi))
#define UNPKF2(lo, hi, s) asm("mov.b64 {%0,%1}, %2;" : "=f"(lo), "=f"(hi) : "l"(s))
#define FMA2(d, a, b, c)  asm("fma.rn.f32x2 %0, %1, %2, %3;" : "=l"(d) : "l"(a), "l"(b), "l"(c))

__device__ __forceinline__ uint32_t smem_u32(const void* p) {
    uint32_t a;
    asm("{ .reg .u64 t; cvta.to.shared.u64 t, %1; cvt.u32.u64 %0, t; }" : "=r"(a) : "l"(p));
    return a;
}

#define LDSM_X4(r0, r1, r2, r3, addr) \
    asm volatile("ldmatrix.sync.aligned.m8n8.x4.shared.b16 {%0,%1,%2,%3}, [%4];" \
                 : "=r"(r0), "=r"(r1), "=r"(r2), "=r"(r3) : "r"(addr))

#define MMA16816(ac, a0, a1, a2, a3, b0, b1) \
    asm volatile("mma.sync.aligned.m16n8k16.row.col.f32.bf16.bf16.f32 " \
                 "{%0,%1,%2,%3}, {%4,%5,%6,%7}, {%8,%9}, {%0,%1,%2,%3};" \
                 : "+f"((ac)[0]), "+f"((ac)[1]), "+f"((ac)[2]), "+f"((ac)[3]) \
                 : "r"(a0), "r"(a1), "r"(a2), "r"(a3), "r"(b0), "r"(b1))

// ---------------- scratch -----------------------------------------------------
__device__ float g_xt[BB * XTB];               // padded NHWC x (zero border, ~20.5MB)
__device__ int    g_pidx[BB * K2 * HW];        // clamped base idx (premul by 64)
__device__ float4 g_pw[BB * K2 * HW];          // masked bilinear weights
__device__ float  g_owt[CC * K2 * 20];
__device__ ushort_t g_bst[K2 * 2 * OO * 72];   // conv_w bf16 [tap][hi/lo][o][72]

// ---------------- transpose NCHW -> padded NHWC --------------------------------
__global__ void transpose_x_kernel(const float* __restrict__ x, float* __restrict__ xt) {
    __shared__ float tile[32][33];
    int blk = blockIdx.x;
    int pt = blk % 288, ct = (blk / 288) & 1, b = blk / 576;
    int lx = threadIdx.x & 31, ly = threadIdx.x >> 5;
    int p0 = pt * 32, c0 = ct * 32;
    int h = p0 / WW, w0 = p0 - h * WW;      // 32-px tile lies within one row
    const float* xb = x + (size_t)(b * CC + c0) * HW + p0;
#pragma unroll
    for (int i = 0; i < 4; i++) {
        int cc = ly + 8 * i;
        tile[cc][lx] = xb[(size_t)cc * HW + lx];
    }
    __syncthreads();
    float* xo = xt + (size_t)b * XTB + ((size_t)(h + 2) * WP + (w0 + 2)) * CC + c0;
#pragma unroll
    for (int i = 0; i < 4; i++) {
        int pp = ly + 8 * i;
        xo[(size_t)pp * CC + lx] = tile[lx][pp];
    }
}

// ---------------- weight prep ---------------------------------------------------
__global__ void build_weights_kernel(const float* __restrict__ cw,
                                     const float* __restrict__ ow,
                                     ushort_t* __restrict__ bst,
                                     float* __restrict__ owt) {
    int idx = blockIdx.x * 256 + threadIdx.x;
    if (idx < K2 * OO * CC) {
        int k = idx / (OO * CC);
        int r = idx % (OO * CC);
        int o = r / CC;
        int c = r % CC;
        float v = cw[(size_t)(o * CC + c) * K2 + k];
        __nv_bfloat16 h = __float2bfloat16(v);
        __nv_bfloat16 l = __float2bfloat16(v - __bfloat162float(h));
        bst[((size_t)(k * 2 + 0) * OO + o) * 72 + c] = *(ushort_t*)&h;
        bst[((size_t)(k * 2 + 1) * OO + o) * 72 + c] = *(ushort_t*)&l;
    }
    if (idx < NOFF * CC * K2) {
        int j = idx / (CC * K2);
        int r = idx % (CC * K2);
        int c = r / K2;
        int k = r % K2;
        owt[(c * K2 + k) * 20 + j] = ow[idx];
    }
}

// ---------------- offset conv + position/weight precompute ---------------------
__global__ void __launch_bounds__(256) offset_conv_kernel(
    const float* __restrict__ x, const float* __restrict__ owt,
    const float* __restrict__ ob, int* __restrict__ pidx, float4* __restrict__ pw)
{
    __shared__ float ws[CC * K2 * 20];
    __shared__ float bs[NOFF];
    int tid = threadIdx.x;
    for (int i = tid; i < CC * K2 * 20; i += 256) ws[i] = owt[i];
    if (tid < NOFF) bs[tid] = ob[tid];
    __syncthreads();

    int flat = blockIdx.x * 256 + tid;
    int b = flat / HW, p = flat % HW;
    int h = p / WW, w = p % WW;
    const float* x0 = x + (size_t)b * CC * HW;

    ull a0[9];
#pragma unroll
    for (int j = 0; j < 9; j++) a0[j] = 0ull;

    int yy[3], xx[3]; bool vy[3], vx[3];
#pragma unroll
    for (int d = 0; d < 3; d++) {
        yy[d] = h + d - 1; vy[d] = (unsigned)yy[d] < (unsigned)HH;
        xx[d] = w + d - 1; vx[d] = (unsigned)xx[d] < (unsigned)WW;
    }
    for (int c = 0; c < CC; c++) {
        float xv[9];
        const float* xc = x0 + (size_t)c * HW;
#pragma unroll
        for (int dy = 0; dy < 3; dy++)
#pragma unroll
            for (int dx = 0; dx < 3; dx++) {
                int i = dy * 3 + dx;
                xv[i] = (vy[dy] && vx[dx]) ? xc[yy[dy] * WW + xx[dx]] : 0.f;
            }
#pragma unroll
        for (int i = 0; i < 9; i++) {
            const float* row = ws + (c * K2 + i) * 20;
            ull s0;
            PACKF2(s0, xv[i], xv[i]);
#pragma unroll
            for (int j = 0; j < 9; j++) {
                ull wv = *(const ull*)(row + 2 * j);
                FMA2(a0[j], s0, wv, a0[j]);
            }
        }
    }
    // per-tap position/weight precompute
#pragma unroll
    for (int t = 0; t < 9; t++) {
        float dy, dx;
        UNPKF2(dy, dx, a0[t]);
        dy += bs[2 * t];
        dx += bs[2 * t + 1];
        float py = (float)(h - 1 + t / 3) + dy;
        float qx = (float)(w - 1 + t % 3) + dx;
        float fy = floorf(py), fx = floorf(qx);
        int y0 = (int)fy, x0i = (int)fx;
        float wy = py - fy, wx = qx - fx;
        bool vy0 = (unsigned)y0 < (unsigned)HH;
        bool vy1 = (unsigned)(y0 + 1) < (unsigned)HH;
        bool vx0 = (unsigned)x0i < (unsigned)WW;
        bool vx1 = (unsigned)(x0i + 1) < (unsigned)WW;
        float w00 = (vy0 && vx0) ? (1.f - wy) * (1.f - wx) : 0.f;
        float w01 = (vy0 && vx1) ? (1.f - wy) * wx         : 0.f;
        float w10 = (vy1 && vx0) ? wy * (1.f - wx)         : 0.f;
        float w11 = (vy1 && vx1) ? wy * wx                 : 0.f;
        int yc = min(max(y0, -2), 95);
        int xc = min(max(x0i, -2), 95);
        size_t gp = ((size_t)(b * 9 + t)) * HW + p;
        pidx[gp] = ((yc + 2) * WP + (xc + 2)) * CC;
        pw[gp]   = make_float4(w00, w01, w10, w11);
    }
}

// ---------------- fused: precomputed gather -> bf16 split -> HMMA ---------------
// 256 thr, tile 128 px x 64 out. Double-buffered A (hi/lo) and B (hi/lo).
#define A_BUF 36864      // bytes: 2 splits x 128 x 144
#define SM_B  73728
#define B_BUF 18432      // bytes: 2 splits x 64 x 144
#define SM_TOT (SM_B + 2 * B_BUF)   // 110592

__global__ void __launch_bounds__(256, 2)
fused_mma_kernel(const float* __restrict__ xt, const int* __restrict__ pidx,
                 const float4* __restrict__ pw, const ushort_t* __restrict__ bst,
                 const float* __restrict__ cb, float* __restrict__ out)
{
    extern __shared__ char smc[];
    uint32_t sbase = smem_u32(smc);
    int tid = threadIdx.x, wid = tid >> 5, lane = tid & 31;
    int b  = blockIdx.x / 72;
    int p0 = (blockIdx.x % 72) * 128;

    const float* xt_b = xt + (size_t)b * XTB;
    int c2 = 2 * lane;

    float acc[8][4];
#pragma unroll
    for (int i = 0; i < 8; i++)
#pragma unroll
        for (int j = 0; j < 4; j++) acc[i][j] = 0.f;

    int lr = lane & 7;
    uint32_t aoff = (uint32_t)((lr + ((lane >> 3) & 1) * 8) * 144 + (lane >> 4) * 16);
    uint32_t boff = (uint32_t)((lr + (lane >> 4) * 8) * 144 + ((lane >> 3) & 1) * 16);

    // ---- helpers as lambdas ----
    auto stageB = [&](int k, int buf) {
        const uint4* src = (const uint4*)(bst + (size_t)k * 9216);
        uint4* dst = (uint4*)(smc + SM_B + buf * B_BUF);
        for (int i = tid; i < 1152; i += 256) dst[i] = src[i];
    };
    auto fill = [&](int k, int buf) {
        const int*    pi = pidx + ((size_t)(b * 9 + k)) * HW + p0;
        const float4* pv = pw   + ((size_t)(b * 9 + k)) * HW + p0;
        char* Ab = smc + buf * A_BUF;
#pragma unroll 4
        for (int j = 0; j < 16; j++) {
            int px = wid + 8 * j;
            int idx = __ldg(pi + px);
            float4 w4 = __ldg(pv + px);
            const float* base = xt_b + idx + c2;
            float2 g00 = *(const float2*)(base);
            float2 g01 = *(const float2*)(base + CC);
            float2 g10 = *(const float2*)(base + WP * CC);
            float2 g11 = *(const float2*)(base + WP * CC + CC);
            float sx = g00.x*w4.x + g01.x*w4.y + g10.x*w4.z + g11.x*w4.w;
            float sy = g00.y*w4.x + g01.y*w4.y + g10.y*w4.z + g11.y*w4.w;
            uint32_t hp, lp;
            asm("cvt.rn.bf16x2.f32 %0, %1, %2;" : "=r"(hp) : "f"(sy), "f"(sx));
            float hx = __uint_as_float(hp << 16);
            float hy = __uint_as_float(hp & 0xffff0000u);
            asm("cvt.rn.bf16x2.f32 %0, %1, %2;" : "=r"(lp) : "f"(sy - hy), "f"(sx - hx));
            uint32_t ao = (uint32_t)(px * 144 + lane * 4);
            *(uint32_t*)(Ab + ao)         = hp;
            *(uint32_t*)(Ab + 18432 + ao) = lp;
        }
    };

    // prologue
    stageB(0, 0);
    fill(0, 0);
    __syncthreads();

    for (int k = 0; k < 9; k++) {
        int buf = k & 1;
        // ---- MMA(k) ----
        uint32_t aH = sbase + buf * A_BUF + (uint32_t)(wid * 16 * 144) + aoff;
        uint32_t aL = aH + 18432;
        uint32_t bH = sbase + SM_B + buf * B_BUF + boff;
        uint32_t bL = bH + 9216;
#pragma unroll
        for (int ks = 0; ks < 4; ks++) {
            uint32_t ah0, ah1, ah2, ah3, al0, al1, al2, al3;
            LDSM_X4(ah0, ah1, ah2, ah3, aH + ks * 32);
            LDSM_X4(al0, al1, al2, al3, aL + ks * 32);
            uint32_t bh[4][4];
#pragma unroll
            for (int q = 0; q < 4; q++)
                LDSM_X4(bh[q][0], bh[q][1], bh[q][2], bh[q][3],
                        bH + (uint32_t)(q * 2304) + ks * 32);
#pragma unroll
            for (int nt = 0; nt < 8; nt++) {
                uint32_t* bq = bh[nt >> 1];
                int e = (nt & 1) * 2;
                MMA16816(acc[nt], ah0, ah1, ah2, ah3, bq[e], bq[e + 1]);
            }
#pragma unroll
            for (int nt = 0; nt < 8; nt++) {
                uint32_t* bq = bh[nt >> 1];
                int e = (nt & 1) * 2;
                MMA16816(acc[nt], al0, al1, al2, al3, bq[e], bq[e + 1]);
            }
            uint32_t bl[4][4];
#pragma unroll
            for (int q = 0; q < 4; q++)
                LDSM_X4(bl[q][0], bl[q][1], bl[q][2], bl[q][3],
                        bL + (uint32_t)(q * 2304) + ks * 32);
#pragma unroll
            for (int nt = 0; nt < 8; nt++) {
                uint32_t* bq = bl[nt >> 1];
                int e = (nt & 1) * 2;
                MMA16816(acc[nt], ah0, ah1, ah2, ah3, bq[e], bq[e + 1]);
            }
        }
        // ---- produce next tap ----
        if (k < 8) {
            stageB(k + 1, buf ^ 1);
            fill(k + 1, buf ^ 1);
        }
        __syncthreads();
    }

    // epilogue
    int px0 = p0 + wid * 16 + (lane >> 2);
    int ob0 = 2 * (lane & 3);
    float* outb = out + (size_t)b * OO * HW;
#pragma unroll
    for (int nt = 0; nt < 8; nt++) {
        int o = nt * 8 + ob0;
        float b0 = cb[o], b1 = cb[o + 1];
        outb[(size_t)o * HW + px0]           = acc[nt][0] + b0;
        outb[(size_t)(o + 1) * HW + px0]     = acc[nt][1] + b1;
        outb[(size_t)o * HW + px0 + 8]       = acc[nt][2] + b0;
        outb[(size_t)(o + 1) * HW + px0 + 8] = acc[nt][3] + b1;
    }
}

// ---------------- launch ---------------------------------------------------------
extern "C" void kernel_launch(void* const* d_in, const int* in_sizes, int n_in,
                              void* d_out, int out_size) {
    const float* x  = (const float*)d_in[0];
    const float* ow = (const float*)d_in[1];
    const float* ob = (const float*)d_in[2];
    const float* cw = (const float*)d_in[3];
    const float* cb = (const float*)d_in[4];
    float* out = (float*)d_out;

    float *xt, *owt;
    int* pidx;
    float4* pw;
    ushort_t* bst;
    cudaGetSymbolAddress((void**)&xt,   g_xt);
    cudaGetSymbolAddress((void**)&owt,  g_owt);
    cudaGetSymbolAddress((void**)&pidx, g_pidx);
    cudaGetSymbolAddress((void**)&pw,   g_pw);
    cudaGetSymbolAddress((void**)&bst,  g_bst);

    cudaFuncSetAttribute(fused_mma_kernel,
                         cudaFuncAttributeMaxDynamicSharedMemorySize, SM_TOT);

    transpose_x_kernel<<<4608, 256>>>(x, xt);
    build_weights_kernel<<<144, 256>>>(cw, ow, bst, owt);
    offset_conv_kernel<<<288, 256>>>(x, owt, ob, pidx, pw);
    fused_mma_kernel<<<576, 256, SM_TOT>>>(xt, pidx, pw, bst, cb, out);
}